// round 9
// baseline (speedup 1.0000x reference)
#include <cuda_runtime.h>
#include <cstdint>

#define B_    8
#define V_    100000
#define FIN_  32
#define K_    4
#define FOUT_ 64
#define E_    800000
#define FH    128                       // floats per vertex per half (32f x 4b, j = f*4+bl)
#define HVF   ((size_t)V_ * FH)         // floats per Chebyshev order per half
#define SCAN_B 98                       // scan blocks (98*1024 >= V_)
#define ETILE 16
#define NTILES (V_ / ETILE)             // 6250
#define EGRID 444                       // einsum: 3 blocks/SM (64KB smem) -> one wave
#define SPGRID 592                      // spmm_all: 4 blocks/SM co-resident

// ---- scratch (static device globals; no allocation) ----
__device__ float d_x[4ull * HVF];       // x0T, x1, x2, x3 for current half
__device__ int   d_counts[V_];          // zero at load; re-zeroed by scanscatter each run
__device__ int   d_rowptr[V_ + 1];
__device__ int   d_cursor[V_];
__device__ int   d_ccol[E_];
__device__ float d_cval[E_];
__device__ int   d_agg[SCAN_B];

// grid-barrier state (reset by hist_kernel at the start of every replay)
__device__ unsigned g_count;
__device__ volatile unsigned g_phase;
__device__ unsigned s_count;
__device__ volatile unsigned s_phase;

// ---------------- packed f32x2 helpers ----------------
__device__ __forceinline__ unsigned long long pack2(float a, float b) {
    unsigned long long r;
    asm("mov.b64 %0, {%1, %2};" : "=l"(r) : "f"(a), "f"(b));
    return r;
}
__device__ __forceinline__ unsigned long long fma2(unsigned long long x,
                                                   unsigned long long y,
                                                   unsigned long long c) {
    unsigned long long r;
    asm("fma.rn.f32x2 %0, %1, %2, %3;" : "=l"(r) : "l"(x), "l"(y), "l"(c));
    return r;
}
__device__ __forceinline__ void unpack2(unsigned long long v, float& lo, float& hi) {
    asm("mov.b64 {%0, %1}, %2;" : "=f"(lo), "=f"(hi) : "l"(v));
}

// ---------------- device grid barrier (all blocks co-resident) ----------------
__device__ __forceinline__ void grid_sync(unsigned* cnt, volatile unsigned* ph,
                                          unsigned target, unsigned nb) {
    __threadfence();
    __syncthreads();
    if (threadIdx.x == 0) {
        unsigned t = atomicAdd(cnt, 1);
        if (t == nb - 1) {
            *cnt = 0;
            __threadfence();
            *(unsigned*)ph = target;
        } else {
            while (*ph < target) { }
            __threadfence();
        }
    }
    __syncthreads();
}

// ---------------- 1. hist (+ barrier-state reset for this replay) ----------------
__global__ void hist_kernel(const int* __restrict__ rows) {
    if (blockIdx.x == 0 && threadIdx.x == 0) {
        g_count = 0; *(unsigned*)&g_phase = 0;
        s_count = 0; *(unsigned*)&s_phase = 0;
    }
    int e = blockIdx.x * blockDim.x + threadIdx.x;
    if (e < E_) atomicAdd(&d_counts[rows[e]], 1);
}

// ---------------- 2. scan (lookback) + grid barrier + scatter, one kernel ----------
__device__ __forceinline__ int block_exscan(int v, int* total) {
    const int lane = threadIdx.x & 31;
    const int wid = threadIdx.x >> 5;
    int inc = v;
    #pragma unroll
    for (int o = 1; o < 32; o <<= 1) {
        int n = __shfl_up_sync(0xffffffffu, inc, o);
        if (lane >= o) inc += n;
    }
    __shared__ int wsum[32];
    if (lane == 31) wsum[wid] = inc;
    __syncthreads();
    if (wid == 0) {
        int s = wsum[lane];
        #pragma unroll
        for (int o = 1; o < 32; o <<= 1) {
            int n = __shfl_up_sync(0xffffffffu, s, o);
            if (lane >= o) s += n;
        }
        wsum[lane] = s;
    }
    __syncthreads();
    int excl = inc - v + (wid ? wsum[wid - 1] : 0);
    *total = wsum[31];
    return excl;
}

__global__ __launch_bounds__(1024) void scanscatter_kernel(const int* __restrict__ rows,
                                                           const int* __restrict__ cols,
                                                           const float* __restrict__ vals) {
    const int gtid = blockIdx.x * 1024 + threadIdx.x;
    // --- scan phase (decoupled lookback, all 98 blocks co-resident) ---
    int c = (gtid < V_) ? d_counts[gtid] : 0;
    int total;
    int excl = block_exscan(c, &total);
    __shared__ int s_off;
    if (threadIdx.x == 0) {
        s_off = 0;
        __threadfence();
        atomicExch(&d_agg[blockIdx.x], total + 1);
    }
    __syncthreads();
    if ((int)threadIdx.x < (int)blockIdx.x) {
        int v;
        do { v = atomicAdd(&d_agg[threadIdx.x], 0); } while (v == 0);
        atomicAdd(&s_off, v - 1);
    }
    __syncthreads();
    const int off = s_off;
    if (gtid < V_) {
        int r = excl + off;
        d_rowptr[gtid] = r;
        d_cursor[gtid] = r;
    }
    if (gtid == 0) d_rowptr[V_] = E_;

    // --- all rowptr/cursor visible everywhere ---
    grid_sync(&s_count, &s_phase, 1, SCAN_B);

    // --- scatter phase + cleanup for next replay ---
    const int stride = SCAN_B * 1024;
    for (int i = gtid; i < V_; i += stride) d_counts[i] = 0;
    if (gtid < SCAN_B) d_agg[gtid] = 0;
    for (int e = gtid; e < E_; e += stride) {
        int r = rows[e];
        int p = atomicAdd(&d_cursor[r], 1);
        d_ccol[p] = cols[e];
        d_cval[p] = vals[e];
    }
}

// ---------------- 3. persistent SpMM: all three Chebyshev passes ----------------
// Pass 1: gathers straight from b-major inputs (1 full LDG.128/edge/lane-quad),
//   writes x1 = L x0 and x0T (interleaved [f*4+bl]) via stride-5 smem staging.
// Pass 2/3: y = 2*(L x) - z in interleaved layout.
__global__ __launch_bounds__(256) void spmm_all_kernel(const float* __restrict__ in, int h) {
    __shared__ float st[8][336];
    const int wrp = threadIdx.x >> 5;
    const int lane = threadIdx.x & 31;
    const int bl = lane >> 3;
    const int f0 = (lane & 7) * 4;
    const int p = lane * 4;
    const float* base = in + ((size_t)bl * V_) * FIN_ + f0;

    float* x0T = d_x;
    float* x1g = d_x + HVF;
    float* x2g = d_x + 2 * HVF;
    float* x3g = d_x + 3 * HVF;

    // ---- pass 1 ----
    for (int v = blockIdx.x * 8 + wrp; v < V_; v += SPGRID * 8) {
        const int s = __ldg(&d_rowptr[v]);
        const int e = __ldg(&d_rowptr[v + 1]);
        float4 aA = make_float4(0.f, 0.f, 0.f, 0.f);
        float4 aB = make_float4(0.f, 0.f, 0.f, 0.f);
        int i = s;
        for (; i + 1 < e; i += 2) {
            int   c0 = __ldg(&d_ccol[i]);
            int   c1 = __ldg(&d_ccol[i + 1]);
            float w0 = __ldg(&d_cval[i]);
            float w1 = __ldg(&d_cval[i + 1]);
            float4 u = __ldg(reinterpret_cast<const float4*>(base + (size_t)c0 * FIN_));
            float4 q = __ldg(reinterpret_cast<const float4*>(base + (size_t)c1 * FIN_));
            aA.x = fmaf(w0, u.x, aA.x); aA.y = fmaf(w0, u.y, aA.y);
            aA.z = fmaf(w0, u.z, aA.z); aA.w = fmaf(w0, u.w, aA.w);
            aB.x = fmaf(w1, q.x, aB.x); aB.y = fmaf(w1, q.y, aB.y);
            aB.z = fmaf(w1, q.z, aB.z); aB.w = fmaf(w1, q.w, aB.w);
        }
        if (i < e) {
            int   c0 = __ldg(&d_ccol[i]);
            float w0 = __ldg(&d_cval[i]);
            float4 u = __ldg(reinterpret_cast<const float4*>(base + (size_t)c0 * FIN_));
            aA.x = fmaf(w0, u.x, aA.x); aA.y = fmaf(w0, u.y, aA.y);
            aA.z = fmaf(w0, u.z, aA.z); aA.w = fmaf(w0, u.w, aA.w);
        }
        aA.x += aB.x; aA.y += aB.y; aA.z += aB.z; aA.w += aB.w;

        float4 o0 = __ldg(reinterpret_cast<const float4*>(base + (size_t)v * FIN_));

        float* s1 = st[wrp];
        float* s0 = st[wrp] + 168;
        s1[(f0 + 0) * 5 + bl] = aA.x; s1[(f0 + 1) * 5 + bl] = aA.y;
        s1[(f0 + 2) * 5 + bl] = aA.z; s1[(f0 + 3) * 5 + bl] = aA.w;
        s0[(f0 + 0) * 5 + bl] = o0.x; s0[(f0 + 1) * 5 + bl] = o0.y;
        s0[(f0 + 2) * 5 + bl] = o0.z; s0[(f0 + 3) * 5 + bl] = o0.w;
        __syncwarp();
        float4 r1, r0;
        r1.x = s1[5 * lane + 0]; r1.y = s1[5 * lane + 1];
        r1.z = s1[5 * lane + 2]; r1.w = s1[5 * lane + 3];
        r0.x = s0[5 * lane + 0]; r0.y = s0[5 * lane + 1];
        r0.z = s0[5 * lane + 2]; r0.w = s0[5 * lane + 3];
        __syncwarp();
        *reinterpret_cast<float4*>(&x1g[(size_t)v * FH + p]) = r1;
        *reinterpret_cast<float4*>(&x0T[(size_t)v * FH + p]) = r0;
    }
    grid_sync(&g_count, &g_phase, (unsigned)(h * 2 + 1), SPGRID);

    // ---- pass 2 & 3 ----
    #pragma unroll 1
    for (int pass = 0; pass < 2; pass++) {
        const float* x = (pass == 0) ? x1g : x2g;
        const float* z = (pass == 0) ? x0T : x1g;
        float* y = (pass == 0) ? x2g : x3g;
        for (int v = blockIdx.x * 8 + wrp; v < V_; v += SPGRID * 8) {
            const int s = __ldg(&d_rowptr[v]);
            const int e = __ldg(&d_rowptr[v + 1]);
            float4 a0 = make_float4(0.f, 0.f, 0.f, 0.f);
            float4 a1 = make_float4(0.f, 0.f, 0.f, 0.f);
            int i = s;
            for (; i + 1 < e; i += 2) {
                int   c0 = __ldg(&d_ccol[i]);
                int   c1 = __ldg(&d_ccol[i + 1]);
                float w0 = __ldg(&d_cval[i]);
                float w1 = __ldg(&d_cval[i + 1]);
                float4 u = __ldg(reinterpret_cast<const float4*>(&x[(size_t)c0 * FH + p]));
                float4 q = __ldg(reinterpret_cast<const float4*>(&x[(size_t)c1 * FH + p]));
                a0.x = fmaf(w0, u.x, a0.x); a0.y = fmaf(w0, u.y, a0.y);
                a0.z = fmaf(w0, u.z, a0.z); a0.w = fmaf(w0, u.w, a0.w);
                a1.x = fmaf(w1, q.x, a1.x); a1.y = fmaf(w1, q.y, a1.y);
                a1.z = fmaf(w1, q.z, a1.z); a1.w = fmaf(w1, q.w, a1.w);
            }
            if (i < e) {
                int   c0 = __ldg(&d_ccol[i]);
                float w0 = __ldg(&d_cval[i]);
                float4 u = __ldg(reinterpret_cast<const float4*>(&x[(size_t)c0 * FH + p]));
                a0.x = fmaf(w0, u.x, a0.x); a0.y = fmaf(w0, u.y, a0.y);
                a0.z = fmaf(w0, u.z, a0.z); a0.w = fmaf(w0, u.w, a0.w);
            }
            float4 zv = __ldg(reinterpret_cast<const float4*>(&z[(size_t)v * FH + p]));
            float4 r;
            r.x = 2.f * (a0.x + a1.x) - zv.x;
            r.y = 2.f * (a0.y + a1.y) - zv.y;
            r.z = 2.f * (a0.z + a1.z) - zv.z;
            r.w = 2.f * (a0.w + a1.w) - zv.w;
            *reinterpret_cast<float4*>(&y[(size_t)v * FH + p]) = r;
        }
        if (pass == 0) grid_sync(&g_count, &g_phase, (unsigned)(h * 2 + 2), SPGRID);
    }
}

// ---------------- 4. persistent einsum ----------------
__global__ __launch_bounds__(256) void einsum_kernel(const float* __restrict__ w,
                                                     const float* __restrict__ bias,
                                                     float* __restrict__ out, int h) {
    extern __shared__ __align__(16) float sm[];
    float* ws = sm;                 // 8192 floats
    float* xs = sm + 8192;          // ETILE * 512 floats

    const int t = threadIdx.x;
    #pragma unroll
    for (int i = 0; i < 32; i++) ws[i * 256 + t] = w[i * 256 + t];

    const int g = t >> 6;
    const int o = t & 63;
    const float bo = __ldg(&bias[o]);

    for (int tile = blockIdx.x; tile < NTILES; tile += EGRID) {
        __syncthreads();
        const int vbase = tile * ETILE;
        #pragma unroll
        for (int i = 0; i < 8; i++) {
            int idx = i * 256 + t;
            int vert = idx >> 7;
            int rem = idx & 127;
            int k = rem >> 5;
            int j4 = rem & 31;
            *reinterpret_cast<float4*>(&xs[vert * 512 + k * 128 + j4 * 4]) =
                *reinterpret_cast<const float4*>(
                    &d_x[(size_t)k * HVF + (size_t)(vbase + vert) * FH + j4 * 4]);
        }
        __syncthreads();

        const float* xb = xs + g * 4 * 512;
        unsigned long long a[4][2] = {{0ull,0ull},{0ull,0ull},{0ull,0ull},{0ull,0ull}};
        #pragma unroll 8
        for (int f = 0; f < FIN_; f++) {
            #pragma unroll
            for (int k = 0; k < K_; k++) {
                float wv = ws[f * 256 + k * 64 + o];
                unsigned long long wp = pack2(wv, wv);
                #pragma unroll
                for (int j = 0; j < 4; j++) {
                    ulonglong2 pr = *reinterpret_cast<const ulonglong2*>(
                        &xb[j * 512 + k * 128 + f * 4]);
                    a[j][0] = fma2(pr.x, wp, a[j][0]);
                    a[j][1] = fma2(pr.y, wp, a[j][1]);
                }
            }
        }

        #pragma unroll
        for (int j = 0; j < 4; j++) {
            const int v = vbase + g * 4 + j;
            float b0, b1, b2, b3;
            unpack2(a[j][0], b0, b1);
            unpack2(a[j][1], b2, b3);
            out[((size_t)(h * 4 + 0) * V_ + v) * FOUT_ + o] = b0 + bo;
            out[((size_t)(h * 4 + 1) * V_ + v) * FOUT_ + o] = b1 + bo;
            out[((size_t)(h * 4 + 2) * V_ + v) * FOUT_ + o] = b2 + bo;
            out[((size_t)(h * 4 + 3) * V_ + v) * FOUT_ + o] = b3 + bo;
        }
    }
}

// ---------------- launch ----------------
extern "C" void kernel_launch(void* const* d_in, const int* in_sizes, int n_in,
                              void* d_out, int out_size) {
    const float* inputs = (const float*)d_in[0];
    const int*   rows   = (const int*)d_in[1];
    const int*   cols   = (const int*)d_in[2];
    const float* vals   = (const float*)d_in[3];
    const float* weight = (const float*)d_in[4];
    const float* bias   = (const float*)d_in[5];
    float* out = (float*)d_out;

    static bool attr_set = false;
    if (!attr_set) {
        cudaFuncSetAttribute(einsum_kernel,
                             cudaFuncAttributeMaxDynamicSharedMemorySize,
                             (8192 + ETILE * 512) * 4);
        attr_set = true;
    }

    hist_kernel<<<(E_ + 255) / 256, 256>>>(rows);                       // 1
    scanscatter_kernel<<<SCAN_B, 1024>>>(rows, cols, vals);             // 2
    for (int h = 0; h < 2; h++) {
        const float* in_h = inputs + (size_t)h * 4 * V_ * FIN_;
        spmm_all_kernel<<<SPGRID, 256>>>(in_h, h);                      // 3 / 5
        einsum_kernel<<<EGRID, 256, (8192 + ETILE * 512) * 4>>>(weight, bias, out, h); // 4 / 6
    }
}

// round 10
// speedup vs baseline: 1.1204x; 1.1204x over previous
#include <cuda_runtime.h>
#include <cstdint>

#define B_    8
#define V_    100000
#define FIN_  32
#define K_    4
#define FOUT_ 64
#define E_    800000
#define FH    128                       // floats per vertex per half (32f x 4b, j = f*4+bl)
#define HVF   ((size_t)V_ * FH)         // floats per Chebyshev order per half
#define SCAN_B 98                       // scan blocks (98*1024 >= V_)

// ---- scratch (static device globals; no allocation) ----
__device__ float d_x[4ull * HVF];       // x0T, x1, x2, x3 for current half
__device__ int   d_counts[V_];          // zero at load; re-zeroed by scanscatter each run
__device__ int   d_rowptr[V_ + 1];
__device__ int   d_cursor[V_];
__device__ int   d_ccol[E_];
__device__ float d_cval[E_];
__device__ int   d_agg[SCAN_B];

// barrier state for scanscatter (reset by hist_kernel every replay)
__device__ unsigned s_count;
__device__ volatile unsigned s_phase;

// ---------------- packed f32x2 helpers ----------------
__device__ __forceinline__ unsigned long long pack2(float a, float b) {
    unsigned long long r;
    asm("mov.b64 %0, {%1, %2};" : "=l"(r) : "f"(a), "f"(b));
    return r;
}
__device__ __forceinline__ unsigned long long fma2(unsigned long long x,
                                                   unsigned long long y,
                                                   unsigned long long c) {
    unsigned long long r;
    asm("fma.rn.f32x2 %0, %1, %2, %3;" : "=l"(r) : "l"(x), "l"(y), "l"(c));
    return r;
}
__device__ __forceinline__ void unpack2(unsigned long long v, float& lo, float& hi) {
    asm("mov.b64 {%0, %1}, %2;" : "=f"(lo), "=f"(hi) : "l"(v));
}

// ---------------- 1. hist (+ barrier-state reset) ----------------
__global__ void hist_kernel(const int* __restrict__ rows) {
    if (blockIdx.x == 0 && threadIdx.x == 0) {
        s_count = 0; *(unsigned*)&s_phase = 0;
    }
    int e = blockIdx.x * blockDim.x + threadIdx.x;
    if (e < E_) atomicAdd(&d_counts[rows[e]], 1);
}

// ---------------- 2. scan (lookback) + grid barrier + scatter ----------------
__device__ __forceinline__ int block_exscan(int v, int* total) {
    const int lane = threadIdx.x & 31;
    const int wid = threadIdx.x >> 5;
    int inc = v;
    #pragma unroll
    for (int o = 1; o < 32; o <<= 1) {
        int n = __shfl_up_sync(0xffffffffu, inc, o);
        if (lane >= o) inc += n;
    }
    __shared__ int wsum[32];
    if (lane == 31) wsum[wid] = inc;
    __syncthreads();
    if (wid == 0) {
        int s = wsum[lane];
        #pragma unroll
        for (int o = 1; o < 32; o <<= 1) {
            int n = __shfl_up_sync(0xffffffffu, s, o);
            if (lane >= o) s += n;
        }
        wsum[lane] = s;
    }
    __syncthreads();
    int excl = inc - v + (wid ? wsum[wid - 1] : 0);
    *total = wsum[31];
    return excl;
}

__global__ __launch_bounds__(1024) void scanscatter_kernel(const int* __restrict__ rows,
                                                           const int* __restrict__ cols,
                                                           const float* __restrict__ vals) {
    const int gtid = blockIdx.x * 1024 + threadIdx.x;
    int c = (gtid < V_) ? d_counts[gtid] : 0;
    int total;
    int excl = block_exscan(c, &total);
    __shared__ int s_off;
    if (threadIdx.x == 0) {
        s_off = 0;
        __threadfence();
        atomicExch(&d_agg[blockIdx.x], total + 1);
    }
    __syncthreads();
    if ((int)threadIdx.x < (int)blockIdx.x) {
        int v;
        do { v = atomicAdd(&d_agg[threadIdx.x], 0); } while (v == 0);
        atomicAdd(&s_off, v - 1);
    }
    __syncthreads();
    const int off = s_off;
    if (gtid < V_) {
        int r = excl + off;
        d_rowptr[gtid] = r;
        d_cursor[gtid] = r;
    }
    if (gtid == 0) d_rowptr[V_] = E_;

    // grid barrier: rowptr/cursor visible everywhere before scatter
    __threadfence();
    __syncthreads();
    if (threadIdx.x == 0) {
        unsigned t = atomicAdd(&s_count, 1);
        if (t == SCAN_B - 1) {
            s_count = 0;
            __threadfence();
            *(unsigned*)&s_phase = 1;
        } else {
            while (s_phase < 1) { }
            __threadfence();
        }
    }
    __syncthreads();

    const int stride = SCAN_B * 1024;
    for (int i = gtid; i < V_; i += stride) d_counts[i] = 0;
    if (gtid < SCAN_B) d_agg[gtid] = 0;
    for (int e = gtid; e < E_; e += stride) {
        int r = rows[e];
        int p = atomicAdd(&d_cursor[r], 1);
        d_ccol[p] = cols[e];
        d_cval[p] = vals[e];
    }
}

// ---------------- 3. SpMM pass 1 + transpose (per batch-half) ----------------
__global__ __launch_bounds__(256) void spmm1t_kernel(const float* __restrict__ in, int h) {
    __shared__ float st[8][336];
    const int wrp = threadIdx.x >> 5;
    const int lane = threadIdx.x & 31;
    const int v = blockIdx.x * 8 + wrp;
    const int bl = lane >> 3;
    const int f0 = (lane & 7) * 4;
    const float* base = in + ((size_t)(h * 4 + bl) * V_) * FIN_ + f0;

    const int s = __ldg(&d_rowptr[v]);
    const int e = __ldg(&d_rowptr[v + 1]);

    float4 aA = make_float4(0.f, 0.f, 0.f, 0.f);
    float4 aB = make_float4(0.f, 0.f, 0.f, 0.f);
    int i = s;
    for (; i + 1 < e; i += 2) {
        int   c0 = __ldg(&d_ccol[i]);
        int   c1 = __ldg(&d_ccol[i + 1]);
        float w0 = __ldg(&d_cval[i]);
        float w1 = __ldg(&d_cval[i + 1]);
        float4 u = __ldg(reinterpret_cast<const float4*>(base + (size_t)c0 * FIN_));
        float4 q = __ldg(reinterpret_cast<const float4*>(base + (size_t)c1 * FIN_));
        aA.x = fmaf(w0, u.x, aA.x); aA.y = fmaf(w0, u.y, aA.y);
        aA.z = fmaf(w0, u.z, aA.z); aA.w = fmaf(w0, u.w, aA.w);
        aB.x = fmaf(w1, q.x, aB.x); aB.y = fmaf(w1, q.y, aB.y);
        aB.z = fmaf(w1, q.z, aB.z); aB.w = fmaf(w1, q.w, aB.w);
    }
    if (i < e) {
        int   c0 = __ldg(&d_ccol[i]);
        float w0 = __ldg(&d_cval[i]);
        float4 u = __ldg(reinterpret_cast<const float4*>(base + (size_t)c0 * FIN_));
        aA.x = fmaf(w0, u.x, aA.x); aA.y = fmaf(w0, u.y, aA.y);
        aA.z = fmaf(w0, u.z, aA.z); aA.w = fmaf(w0, u.w, aA.w);
    }
    aA.x += aB.x; aA.y += aB.y; aA.z += aB.z; aA.w += aB.w;

    float4 o0 = __ldg(reinterpret_cast<const float4*>(base + (size_t)v * FIN_));

    float* s1 = st[wrp];
    float* s0 = st[wrp] + 168;
    s1[(f0 + 0) * 5 + bl] = aA.x; s1[(f0 + 1) * 5 + bl] = aA.y;
    s1[(f0 + 2) * 5 + bl] = aA.z; s1[(f0 + 3) * 5 + bl] = aA.w;
    s0[(f0 + 0) * 5 + bl] = o0.x; s0[(f0 + 1) * 5 + bl] = o0.y;
    s0[(f0 + 2) * 5 + bl] = o0.z; s0[(f0 + 3) * 5 + bl] = o0.w;
    __syncwarp();

    float4 r1, r0;
    r1.x = s1[5 * lane + 0]; r1.y = s1[5 * lane + 1];
    r1.z = s1[5 * lane + 2]; r1.w = s1[5 * lane + 3];
    r0.x = s0[5 * lane + 0]; r0.y = s0[5 * lane + 1];
    r0.z = s0[5 * lane + 2]; r0.w = s0[5 * lane + 3];

    float* x0T = d_x;
    float* x1g = d_x + HVF;
    *reinterpret_cast<float4*>(&x1g[(size_t)v * FH + lane * 4]) = r1;
    *reinterpret_cast<float4*>(&x0T[(size_t)v * FH + lane * 4]) = r0;
}

// ---------------- 4. SpMM passes 2/3 (interleaved layout): y = 2*(L x) - z ----------
__global__ __launch_bounds__(256) void spmm2_kernel(const float* __restrict__ x,
                                                    const float* __restrict__ z,
                                                    float* __restrict__ y) {
    const int wrp = threadIdx.x >> 5;
    const int lane = threadIdx.x & 31;
    const int v = blockIdx.x * 8 + wrp;
    const int p = lane * 4;
    const int s = __ldg(&d_rowptr[v]);
    const int e = __ldg(&d_rowptr[v + 1]);

    float4 a0 = make_float4(0.f, 0.f, 0.f, 0.f);
    float4 a1 = make_float4(0.f, 0.f, 0.f, 0.f);
    int i = s;
    for (; i + 1 < e; i += 2) {
        int   c0 = __ldg(&d_ccol[i]);
        int   c1 = __ldg(&d_ccol[i + 1]);
        float w0 = __ldg(&d_cval[i]);
        float w1 = __ldg(&d_cval[i + 1]);
        float4 u = __ldg(reinterpret_cast<const float4*>(&x[(size_t)c0 * FH + p]));
        float4 q = __ldg(reinterpret_cast<const float4*>(&x[(size_t)c1 * FH + p]));
        a0.x = fmaf(w0, u.x, a0.x); a0.y = fmaf(w0, u.y, a0.y);
        a0.z = fmaf(w0, u.z, a0.z); a0.w = fmaf(w0, u.w, a0.w);
        a1.x = fmaf(w1, q.x, a1.x); a1.y = fmaf(w1, q.y, a1.y);
        a1.z = fmaf(w1, q.z, a1.z); a1.w = fmaf(w1, q.w, a1.w);
    }
    if (i < e) {
        int   c0 = __ldg(&d_ccol[i]);
        float w0 = __ldg(&d_cval[i]);
        float4 u = __ldg(reinterpret_cast<const float4*>(&x[(size_t)c0 * FH + p]));
        a0.x = fmaf(w0, u.x, a0.x); a0.y = fmaf(w0, u.y, a0.y);
        a0.z = fmaf(w0, u.z, a0.z); a0.w = fmaf(w0, u.w, a0.w);
    }
    float4 zv = __ldg(reinterpret_cast<const float4*>(&z[(size_t)v * FH + p]));
    float4 r;
    r.x = 2.f * (a0.x + a1.x) - zv.x;
    r.y = 2.f * (a0.y + a1.y) - zv.y;
    r.z = 2.f * (a0.z + a1.z) - zv.z;
    r.w = 2.f * (a0.w + a1.w) - zv.w;
    *reinterpret_cast<float4*>(&y[(size_t)v * FH + p]) = r;
}

// ---------------- 5. einsum: warp owns 4 vertices, thread owns o and o+32 ----------
// x comes straight from global as 16B all-lane-broadcast __ldg (1 request/warp),
// reused in registers across both o-slots. Weights: 32KB smem, conflict-free LDS.32.
__global__ __launch_bounds__(256) void einsum_kernel(const float* __restrict__ w,
                                                     const float* __restrict__ bias,
                                                     float* __restrict__ out, int h) {
    __shared__ float ws[FIN_ * K_ * FOUT_];
    const int t = threadIdx.x;
    #pragma unroll
    for (int i = 0; i < 32; i++) ws[i * 256 + t] = w[i * 256 + t];
    __syncthreads();

    const int wrp = t >> 5;
    const int lane = t & 31;
    const int v0 = blockIdx.x * 32 + wrp * 4;       // 3125 blocks * 32 v = V_
    const float bo0 = __ldg(&bias[lane]);
    const float bo1 = __ldg(&bias[lane + 32]);
    const float* xb = d_x + (size_t)v0 * FH;

    unsigned long long a[4][2][2];                   // [vertex j][o-slot][batch pair]
    #pragma unroll
    for (int j = 0; j < 4; j++)
        #pragma unroll
        for (int s2 = 0; s2 < 2; s2++) { a[j][s2][0] = 0ull; a[j][s2][1] = 0ull; }

    #pragma unroll 2
    for (int f = 0; f < FIN_; f++) {
        #pragma unroll
        for (int k = 0; k < K_; k++) {
            float w0 = ws[f * 256 + k * 64 + lane];
            float w1 = ws[f * 256 + k * 64 + 32 + lane];
            unsigned long long wp0 = pack2(w0, w0);
            unsigned long long wp1 = pack2(w1, w1);
            #pragma unroll
            for (int j = 0; j < 4; j++) {
                ulonglong2 xv = __ldg(reinterpret_cast<const ulonglong2*>(
                    xb + (size_t)k * HVF + j * FH + f * 4));
                a[j][0][0] = fma2(xv.x, wp0, a[j][0][0]);
                a[j][0][1] = fma2(xv.y, wp0, a[j][0][1]);
                a[j][1][0] = fma2(xv.x, wp1, a[j][1][0]);
                a[j][1][1] = fma2(xv.y, wp1, a[j][1][1]);
            }
        }
    }

    #pragma unroll
    for (int j = 0; j < 4; j++) {
        const int v = v0 + j;
        #pragma unroll
        for (int s2 = 0; s2 < 2; s2++) {
            float b0, b1, b2, b3;
            unpack2(a[j][s2][0], b0, b1);
            unpack2(a[j][s2][1], b2, b3);
            const int o = lane + s2 * 32;
            const float bb = s2 ? bo1 : bo0;
            out[((size_t)(h * 4 + 0) * V_ + v) * FOUT_ + o] = b0 + bb;
            out[((size_t)(h * 4 + 1) * V_ + v) * FOUT_ + o] = b1 + bb;
            out[((size_t)(h * 4 + 2) * V_ + v) * FOUT_ + o] = b2 + bb;
            out[((size_t)(h * 4 + 3) * V_ + v) * FOUT_ + o] = b3 + bb;
        }
    }
}

// ---------------- launch ----------------
extern "C" void kernel_launch(void* const* d_in, const int* in_sizes, int n_in,
                              void* d_out, int out_size) {
    const float* inputs = (const float*)d_in[0];
    const int*   rows   = (const int*)d_in[1];
    const int*   cols   = (const int*)d_in[2];
    const float* vals   = (const float*)d_in[3];
    const float* weight = (const float*)d_in[4];
    const float* bias   = (const float*)d_in[5];
    float* out = (float*)d_out;

    float* xbase;
    cudaGetSymbolAddress((void**)&xbase, d_x);

    hist_kernel<<<(E_ + 255) / 256, 256>>>(rows);                   // 1
    scanscatter_kernel<<<SCAN_B, 1024>>>(rows, cols, vals);         // 2

    float* x0T = xbase;
    float* x1 = xbase + HVF;
    float* x2 = xbase + 2 * HVF;
    float* x3 = xbase + 3 * HVF;

    for (int h = 0; h < 2; h++) {
        spmm1t_kernel<<<V_ / 8, 256>>>(inputs, h);    // 3 / 7
        spmm2_kernel<<<V_ / 8, 256>>>(x1, x0T, x2);   // 4 / 8  (ncu sample target)
        spmm2_kernel<<<V_ / 8, 256>>>(x2, x1, x3);    // 5 / 9
        einsum_kernel<<<V_ / 32, 256>>>(weight, bias, out, h);  // 6 / 10
    }
}

// round 11
// speedup vs baseline: 1.4066x; 1.2554x over previous
#include <cuda_runtime.h>
#include <cstdint>

#define B_    8
#define V_    100000
#define FIN_  32
#define K_    4
#define FOUT_ 64
#define E_    800000
#define FH    128                       // floats per vertex per half (32f x 4b, j = f*4+bl)
#define HVF   ((size_t)V_ * FH)         // floats per Chebyshev order per half
#define SCAN_B 98                       // scan blocks (98*1024 >= V_)
#define ESMEM  ((8192 + 8 * 512 * 4) * 4)   // ws 32KB + xst 64KB

// ---- scratch (static device globals; no allocation) ----
__device__ float d_x[4ull * HVF];       // x0T, x1, x2, x3 for current half
__device__ int   d_counts[V_];          // zero at load; re-zeroed by scanscatter each run
__device__ int   d_rowptr[V_ + 1];
__device__ int   d_cursor[V_];
__device__ int   d_ccol[E_];
__device__ float d_cval[E_];
__device__ int   d_agg[SCAN_B];

// barrier state for scanscatter (reset by hist_kernel every replay)
__device__ unsigned s_count;
__device__ volatile unsigned s_phase;

// ---------------- packed f32x2 helpers ----------------
__device__ __forceinline__ unsigned long long pack2(float a, float b) {
    unsigned long long r;
    asm("mov.b64 %0, {%1, %2};" : "=l"(r) : "f"(a), "f"(b));
    return r;
}
__device__ __forceinline__ unsigned long long fma2(unsigned long long x,
                                                   unsigned long long y,
                                                   unsigned long long c) {
    unsigned long long r;
    asm("fma.rn.f32x2 %0, %1, %2, %3;" : "=l"(r) : "l"(x), "l"(y), "l"(c));
    return r;
}
__device__ __forceinline__ void unpack2(unsigned long long v, float& lo, float& hi) {
    asm("mov.b64 {%0, %1}, %2;" : "=f"(lo), "=f"(hi) : "l"(v));
}

// ---------------- 1. hist (+ barrier-state reset) ----------------
__global__ void hist_kernel(const int* __restrict__ rows) {
    if (blockIdx.x == 0 && threadIdx.x == 0) {
        s_count = 0; *(unsigned*)&s_phase = 0;
    }
    int e = blockIdx.x * blockDim.x + threadIdx.x;
    if (e < E_) atomicAdd(&d_counts[rows[e]], 1);
}

// ---------------- 2. scan (lookback) + grid barrier + scatter ----------------
__device__ __forceinline__ int block_exscan(int v, int* total) {
    const int lane = threadIdx.x & 31;
    const int wid = threadIdx.x >> 5;
    int inc = v;
    #pragma unroll
    for (int o = 1; o < 32; o <<= 1) {
        int n = __shfl_up_sync(0xffffffffu, inc, o);
        if (lane >= o) inc += n;
    }
    __shared__ int wsum[32];
    if (lane == 31) wsum[wid] = inc;
    __syncthreads();
    if (wid == 0) {
        int s = wsum[lane];
        #pragma unroll
        for (int o = 1; o < 32; o <<= 1) {
            int n = __shfl_up_sync(0xffffffffu, s, o);
            if (lane >= o) s += n;
        }
        wsum[lane] = s;
    }
    __syncthreads();
    int excl = inc - v + (wid ? wsum[wid - 1] : 0);
    *total = wsum[31];
    return excl;
}

__global__ __launch_bounds__(1024) void scanscatter_kernel(const int* __restrict__ rows,
                                                           const int* __restrict__ cols,
                                                           const float* __restrict__ vals) {
    const int gtid = blockIdx.x * 1024 + threadIdx.x;
    int c = (gtid < V_) ? d_counts[gtid] : 0;
    int total;
    int excl = block_exscan(c, &total);
    __shared__ int s_off;
    if (threadIdx.x == 0) {
        s_off = 0;
        __threadfence();
        atomicExch(&d_agg[blockIdx.x], total + 1);
    }
    __syncthreads();
    if ((int)threadIdx.x < (int)blockIdx.x) {
        int v;
        do { v = atomicAdd(&d_agg[threadIdx.x], 0); } while (v == 0);
        atomicAdd(&s_off, v - 1);
    }
    __syncthreads();
    const int off = s_off;
    if (gtid < V_) {
        int r = excl + off;
        d_rowptr[gtid] = r;
        d_cursor[gtid] = r;
    }
    if (gtid == 0) d_rowptr[V_] = E_;

    // grid barrier: rowptr/cursor visible everywhere before scatter
    __threadfence();
    __syncthreads();
    if (threadIdx.x == 0) {
        unsigned t = atomicAdd(&s_count, 1);
        if (t == SCAN_B - 1) {
            s_count = 0;
            __threadfence();
            *(unsigned*)&s_phase = 1;
        } else {
            while (s_phase < 1) { }
            __threadfence();
        }
    }
    __syncthreads();

    const int stride = SCAN_B * 1024;
    for (int i = gtid; i < V_; i += stride) d_counts[i] = 0;
    if (gtid < SCAN_B) d_agg[gtid] = 0;
    for (int e = gtid; e < E_; e += stride) {
        int r = rows[e];
        int p = atomicAdd(&d_cursor[r], 1);
        d_ccol[p] = cols[e];
        d_cval[p] = vals[e];
    }
}

// ---------------- 3. SpMM pass 1 + transpose (per batch-half) ----------------
__global__ __launch_bounds__(256) void spmm1t_kernel(const float* __restrict__ in, int h) {
    __shared__ float st[8][336];
    const int wrp = threadIdx.x >> 5;
    const int lane = threadIdx.x & 31;
    const int v = blockIdx.x * 8 + wrp;
    const int bl = lane >> 3;
    const int f0 = (lane & 7) * 4;
    const float* base = in + ((size_t)(h * 4 + bl) * V_) * FIN_ + f0;

    const int s = __ldg(&d_rowptr[v]);
    const int e = __ldg(&d_rowptr[v + 1]);

    float4 aA = make_float4(0.f, 0.f, 0.f, 0.f);
    float4 aB = make_float4(0.f, 0.f, 0.f, 0.f);
    int i = s;
    for (; i + 1 < e; i += 2) {
        int   c0 = __ldg(&d_ccol[i]);
        int   c1 = __ldg(&d_ccol[i + 1]);
        float w0 = __ldg(&d_cval[i]);
        float w1 = __ldg(&d_cval[i + 1]);
        float4 u = __ldg(reinterpret_cast<const float4*>(base + (size_t)c0 * FIN_));
        float4 q = __ldg(reinterpret_cast<const float4*>(base + (size_t)c1 * FIN_));
        aA.x = fmaf(w0, u.x, aA.x); aA.y = fmaf(w0, u.y, aA.y);
        aA.z = fmaf(w0, u.z, aA.z); aA.w = fmaf(w0, u.w, aA.w);
        aB.x = fmaf(w1, q.x, aB.x); aB.y = fmaf(w1, q.y, aB.y);
        aB.z = fmaf(w1, q.z, aB.z); aB.w = fmaf(w1, q.w, aB.w);
    }
    if (i < e) {
        int   c0 = __ldg(&d_ccol[i]);
        float w0 = __ldg(&d_cval[i]);
        float4 u = __ldg(reinterpret_cast<const float4*>(base + (size_t)c0 * FIN_));
        aA.x = fmaf(w0, u.x, aA.x); aA.y = fmaf(w0, u.y, aA.y);
        aA.z = fmaf(w0, u.z, aA.z); aA.w = fmaf(w0, u.w, aA.w);
    }
    aA.x += aB.x; aA.y += aB.y; aA.z += aB.z; aA.w += aB.w;

    float4 o0 = __ldg(reinterpret_cast<const float4*>(base + (size_t)v * FIN_));

    float* s1 = st[wrp];
    float* s0 = st[wrp] + 168;
    s1[(f0 + 0) * 5 + bl] = aA.x; s1[(f0 + 1) * 5 + bl] = aA.y;
    s1[(f0 + 2) * 5 + bl] = aA.z; s1[(f0 + 3) * 5 + bl] = aA.w;
    s0[(f0 + 0) * 5 + bl] = o0.x; s0[(f0 + 1) * 5 + bl] = o0.y;
    s0[(f0 + 2) * 5 + bl] = o0.z; s0[(f0 + 3) * 5 + bl] = o0.w;
    __syncwarp();

    float4 r1, r0;
    r1.x = s1[5 * lane + 0]; r1.y = s1[5 * lane + 1];
    r1.z = s1[5 * lane + 2]; r1.w = s1[5 * lane + 3];
    r0.x = s0[5 * lane + 0]; r0.y = s0[5 * lane + 1];
    r0.z = s0[5 * lane + 2]; r0.w = s0[5 * lane + 3];

    float* x0T = d_x;
    float* x1g = d_x + HVF;
    *reinterpret_cast<float4*>(&x1g[(size_t)v * FH + lane * 4]) = r1;
    *reinterpret_cast<float4*>(&x0T[(size_t)v * FH + lane * 4]) = r0;
}

// ---------------- 4. SpMM passes 2/3 (interleaved layout): y = 2*(L x) - z ----------
__global__ __launch_bounds__(256) void spmm2_kernel(const float* __restrict__ x,
                                                    const float* __restrict__ z,
                                                    float* __restrict__ y) {
    const int wrp = threadIdx.x >> 5;
    const int lane = threadIdx.x & 31;
    const int v = blockIdx.x * 8 + wrp;
    const int p = lane * 4;
    const int s = __ldg(&d_rowptr[v]);
    const int e = __ldg(&d_rowptr[v + 1]);

    float4 a0 = make_float4(0.f, 0.f, 0.f, 0.f);
    float4 a1 = make_float4(0.f, 0.f, 0.f, 0.f);
    int i = s;
    for (; i + 1 < e; i += 2) {
        int   c0 = __ldg(&d_ccol[i]);
        int   c1 = __ldg(&d_ccol[i + 1]);
        float w0 = __ldg(&d_cval[i]);
        float w1 = __ldg(&d_cval[i + 1]);
        float4 u = __ldg(reinterpret_cast<const float4*>(&x[(size_t)c0 * FH + p]));
        float4 q = __ldg(reinterpret_cast<const float4*>(&x[(size_t)c1 * FH + p]));
        a0.x = fmaf(w0, u.x, a0.x); a0.y = fmaf(w0, u.y, a0.y);
        a0.z = fmaf(w0, u.z, a0.z); a0.w = fmaf(w0, u.w, a0.w);
        a1.x = fmaf(w1, q.x, a1.x); a1.y = fmaf(w1, q.y, a1.y);
        a1.z = fmaf(w1, q.z, a1.z); a1.w = fmaf(w1, q.w, a1.w);
    }
    if (i < e) {
        int   c0 = __ldg(&d_ccol[i]);
        float w0 = __ldg(&d_cval[i]);
        float4 u = __ldg(reinterpret_cast<const float4*>(&x[(size_t)c0 * FH + p]));
        a0.x = fmaf(w0, u.x, a0.x); a0.y = fmaf(w0, u.y, a0.y);
        a0.z = fmaf(w0, u.z, a0.z); a0.w = fmaf(w0, u.w, a0.w);
    }
    float4 zv = __ldg(reinterpret_cast<const float4*>(&z[(size_t)v * FH + p]));
    float4 r;
    r.x = 2.f * (a0.x + a1.x) - zv.x;
    r.y = 2.f * (a0.y + a1.y) - zv.y;
    r.z = 2.f * (a0.z + a1.z) - zv.z;
    r.w = 2.f * (a0.w + a1.w) - zv.w;
    *reinterpret_cast<float4*>(&y[(size_t)v * FH + p]) = r;
}

// ---------------- 5. einsum: warp owns 4 vertices; per-warp smem staging ----------
// Stage: each warp copies its 4 vertices' 8KB (coalesced LDG.128 -> STS.128,
// warp-private, __syncwarp only). Compute: thread owns o=lane and o=lane+32;
// x read as broadcast LDS.128 (1 wavefront), weights as conflict-free LDS.32.
__global__ __launch_bounds__(256) void einsum_kernel(const float* __restrict__ w,
                                                     const float* __restrict__ bias,
                                                     float* __restrict__ out, int h) {
    extern __shared__ __align__(16) float sm[];
    float*  ws  = sm;                                  // 8192 floats (32KB)
    float4* xst = reinterpret_cast<float4*>(sm + 8192); // 8 warps * 512 float4 (64KB)

    const int t = threadIdx.x;
    #pragma unroll
    for (int i = 0; i < 32; i++) ws[i * 256 + t] = w[i * 256 + t];
    __syncthreads();

    const int wrp = t >> 5;
    const int lane = t & 31;
    const int v0 = blockIdx.x * 32 + wrp * 4;          // 3125 blocks * 32 v = V_
    float4* xw = xst + wrp * 512;                      // this warp's staging slice

    // stage 4 vertices x 4 orders x 32 float4  (layout: [j][k][q], q = f)
    #pragma unroll
    for (int i = 0; i < 16; i++) {
        int idx = i * 32 + lane;                       // 0..511, warp-uniform j,k per instr
        int j = idx >> 7;
        int k = (idx >> 5) & 3;
        int q = idx & 31;
        xw[idx] = __ldg(reinterpret_cast<const float4*>(
            d_x + (size_t)k * HVF + (size_t)(v0 + j) * FH + q * 4));
    }
    __syncwarp();

    const float bo0 = __ldg(&bias[lane]);
    const float bo1 = __ldg(&bias[lane + 32]);

    unsigned long long a[4][2][2];                     // [vertex j][o-slot][batch pair]
    #pragma unroll
    for (int j = 0; j < 4; j++)
        #pragma unroll
        for (int s2 = 0; s2 < 2; s2++) { a[j][s2][0] = 0ull; a[j][s2][1] = 0ull; }

    #pragma unroll 2
    for (int f = 0; f < FIN_; f++) {
        #pragma unroll
        for (int k = 0; k < K_; k++) {
            float w0 = ws[f * 256 + k * 64 + lane];
            float w1 = ws[f * 256 + k * 64 + 32 + lane];
            unsigned long long wp0 = pack2(w0, w0);
            unsigned long long wp1 = pack2(w1, w1);
            #pragma unroll
            for (int j = 0; j < 4; j++) {
                ulonglong2 xv = *reinterpret_cast<const ulonglong2*>(
                    &xw[j * 128 + k * 32 + f]);        // broadcast LDS.128
                a[j][0][0] = fma2(xv.x, wp0, a[j][0][0]);
                a[j][0][1] = fma2(xv.y, wp0, a[j][0][1]);
                a[j][1][0] = fma2(xv.x, wp1, a[j][1][0]);
                a[j][1][1] = fma2(xv.y, wp1, a[j][1][1]);
            }
        }
    }

    #pragma unroll
    for (int j = 0; j < 4; j++) {
        const int v = v0 + j;
        #pragma unroll
        for (int s2 = 0; s2 < 2; s2++) {
            float b0, b1, b2, b3;
            unpack2(a[j][s2][0], b0, b1);
            unpack2(a[j][s2][1], b2, b3);
            const int o = lane + s2 * 32;
            const float bb = s2 ? bo1 : bo0;
            out[((size_t)(h * 4 + 0) * V_ + v) * FOUT_ + o] = b0 + bb;
            out[((size_t)(h * 4 + 1) * V_ + v) * FOUT_ + o] = b1 + bb;
            out[((size_t)(h * 4 + 2) * V_ + v) * FOUT_ + o] = b2 + bb;
            out[((size_t)(h * 4 + 3) * V_ + v) * FOUT_ + o] = b3 + bb;
        }
    }
}

// ---------------- launch ----------------
extern "C" void kernel_launch(void* const* d_in, const int* in_sizes, int n_in,
                              void* d_out, int out_size) {
    const float* inputs = (const float*)d_in[0];
    const int*   rows   = (const int*)d_in[1];
    const int*   cols   = (const int*)d_in[2];
    const float* vals   = (const float*)d_in[3];
    const float* weight = (const float*)d_in[4];
    const float* bias   = (const float*)d_in[5];
    float* out = (float*)d_out;

    float* xbase;
    cudaGetSymbolAddress((void**)&xbase, d_x);

    static bool attr_set = false;
    if (!attr_set) {
        cudaFuncSetAttribute(einsum_kernel,
                             cudaFuncAttributeMaxDynamicSharedMemorySize, ESMEM);
        attr_set = true;
    }

    hist_kernel<<<(E_ + 255) / 256, 256>>>(rows);                   // 1
    scanscatter_kernel<<<SCAN_B, 1024>>>(rows, cols, vals);         // 2

    float* x0T = xbase;
    float* x1 = xbase + HVF;
    float* x2 = xbase + 2 * HVF;
    float* x3 = xbase + 3 * HVF;

    for (int h = 0; h < 2; h++) {
        spmm1t_kernel<<<V_ / 8, 256>>>(inputs, h);    // 3 / 7
        spmm2_kernel<<<V_ / 8, 256>>>(x1, x0T, x2);   // 4 / 8  (ncu sample target)
        spmm2_kernel<<<V_ / 8, 256>>>(x2, x1, x3);    // 5 / 9
        einsum_kernel<<<V_ / 32, 256, ESMEM>>>(weight, bias, out, h);  // 6 / 10
    }
}